// round 15
// baseline (speedup 1.0000x reference)
#include <cuda_runtime.h>
#include <cuda_fp16.h>
#include <cstdint>

// Problem constants
#define NNODES 100000
#define NEDGES 500000
#define DZ     128
#define HID    512
#define NCOLS  1024     // [A | B] per node
#define OUTC   2
#define KTOT   128      // plain fp16 K

// Scratch (static device arrays: allocation-free per harness rules)
__device__ __half g_Ch[(size_t)NNODES * NCOLS];   // C = [A|B] in fp16 (205 MB)
__device__ __half g_A[(size_t)NNODES * KTOT];     // z in fp16 (25.6 MB)
__device__ __half g_B[(size_t)NCOLS  * KTOT];     // W1 reshaped, fp16 (256 KB)

__device__ __forceinline__ uint32_t smem_u32(const void* p) {
    uint32_t a;
    asm("{ .reg .u64 t; cvta.to.shared.u64 t, %1; cvt.u32.u64 %0, t; }"
        : "=r"(a) : "l"(p));
    return a;
}

__device__ __forceinline__ uint2 cvt4_fp16(float4 v) {
    uint16_t h[4];
    h[0] = __half_as_ushort(__float2half_rn(v.x));
    h[1] = __half_as_ushort(__float2half_rn(v.y));
    h[2] = __half_as_ushort(__float2half_rn(v.z));
    h[3] = __half_as_ushort(__float2half_rn(v.w));
    uint2 p;
    p.x = (uint32_t)h[0] | ((uint32_t)h[1] << 16);
    p.y = (uint32_t)h[2] | ((uint32_t)h[3] << 16);
    return p;
}

// ---------------------------------------------------------------------------
// Prep (merged, MLP=4): A-part converts z -> fp16 [NNODES,128];
// B-part reshapes W1 rows -> fp16 [NCOLS,128]. Each thread handles 4
// block-strided items so 4 loads are in flight (hides DRAM latency).
// ---------------------------------------------------------------------------
#define PREP_A_WORK (NNODES * 32)
#define PREP_B_WORK (NCOLS * 32)
#define PREP_TOTAL  (PREP_A_WORK + PREP_B_WORK)   // 3,232,768 = 3157 * 1024

__device__ __forceinline__ void prep_item(int idx, const float* __restrict__ z,
                                          const float* __restrict__ W1) {
    if (idx < PREP_A_WORK) {
        float4 v = __ldg(((const float4*)z) + idx);
        *(uint2*)(g_A + (size_t)idx * 4) = cvt4_fp16(v);
    } else if (idx < PREP_TOTAL) {
        int i2 = idx - PREP_A_WORK;
        int n = i2 >> 5;
        int c4 = i2 & 31;
        const float4* src = (n < HID)
            ? ((const float4*)W1 + n * 64 + c4)
            : ((const float4*)W1 + (n - HID) * 64 + 32 + c4);
        float4 v = __ldg(src);
        *(uint2*)(g_B + (size_t)n * KTOT + c4 * 4) = cvt4_fp16(v);
    }
}

__global__ __launch_bounds__(256)
void prep_kernel(const float* __restrict__ z, const float* __restrict__ W1) {
    int base = blockIdx.x * 1024 + threadIdx.x;
    #pragma unroll
    for (int j = 0; j < 4; j++)
        prep_item(base + j * 256, z, W1);
}

// ---------------------------------------------------------------------------
// HMMA GEMM: C[M,1024] = A[M,128] @ B[1024,128]^T  (+ b1 on cols < 512),
// stored fp16. Tile 128x128x32, 256 threads (8 warps, each 64x32),
// mma.m16n8k16 fp16 (fp32 acc). Full-K prefetch: all 4 stages issued, ONE
// wait+sync, then 4 back-to-back compute stages (disjoint buffers, no WAR).
// SMEM-staged coalesced epilogue.
// ---------------------------------------------------------------------------
#define BM 128
#define BN 128
#define BK 32
#define LDA 40            // smem row stride in halfs (conflict-free ldmatrix)
#define GSTAGE (BM * LDA) // halfs per operand stage = 5120
#define GEMM_SMEM (8 * GSTAGE * 2)   // 4 A-stages + 4 B-stages = 81920 B
#define EPI_LD 136        // epilogue staging row stride (halfs), conflict-free

__global__ __launch_bounds__(256, 2)
void gemm_hmma_kernel(const float* __restrict__ b1) {
    extern __shared__ __half gsm[];
    __half* As = gsm;                 // [4][GSTAGE]
    __half* Bs = gsm + 4 * GSTAGE;    // [4][GSTAGE]

    const int tid  = threadIdx.x;
    const int lane = tid & 31;
    const int wid  = tid >> 5;
    const int wm   = wid >> 2;       // 0..1 -> m offset wm*64
    const int wn   = wid & 3;        // 0..3 -> n offset wn*32
    const int bn   = blockIdx.x * BN;   // x = n-tile so concurrent CTAs share A
    const int bm   = blockIdx.y * BM;

    float acc[4][4][4];
    #pragma unroll
    for (int i = 0; i < 4; i++)
        #pragma unroll
        for (int j = 0; j < 4; j++)
            #pragma unroll
            for (int k = 0; k < 4; k++) acc[i][j][k] = 0.0f;

    const int a_r = lane & 15;
    const int a_k = (lane >> 4) * 8;
    const int b_r = (lane & 7) + (lane >> 4) * 8;
    const int b_k = ((lane >> 3) & 1) * 8;

    auto load_stage = [&](int it, int buf) {
        const int k0 = it * BK;
        #pragma unroll
        for (int j = 0; j < 2; j++) {
            int li  = tid + j * 256;      // 0..511 over 128 rows x 4 chunks
            int row = li >> 2;
            int ch  = (li & 3) * 8;
            uint32_t da = smem_u32(As + buf * GSTAGE + row * LDA + ch);
            const __half* sa = g_A + (size_t)(bm + row) * KTOT + k0 + ch;
            int sz = (bm + row < NNODES) ? 16 : 0;
            asm volatile("cp.async.cg.shared.global [%0], [%1], 16, %2;\n"
                         :: "r"(da), "l"(sa), "r"(sz));
            uint32_t db = smem_u32(Bs + buf * GSTAGE + row * LDA + ch);
            const __half* sb = g_B + (size_t)(bn + row) * KTOT + k0 + ch;
            asm volatile("cp.async.cg.shared.global [%0], [%1], 16;\n"
                         :: "r"(db), "l"(sb));
        }
        asm volatile("cp.async.commit_group;\n");
    };

    auto compute_stage = [&](int buf) {
        const __half* Ab = As + buf * GSTAGE;
        const __half* Bb = Bs + buf * GSTAGE;
        #pragma unroll
        for (int kk = 0; kk < BK; kk += 16) {
            uint32_t af[4][4], bf[2][4];
            #pragma unroll
            for (int mi = 0; mi < 4; mi++) {
                uint32_t addr = smem_u32(Ab + (wm * 64 + mi * 16 + a_r) * LDA + kk + a_k);
                asm volatile("ldmatrix.sync.aligned.m8n8.x4.shared.b16 {%0,%1,%2,%3}, [%4];"
                             : "=r"(af[mi][0]), "=r"(af[mi][1]),
                               "=r"(af[mi][2]), "=r"(af[mi][3]) : "r"(addr));
            }
            #pragma unroll
            for (int pi = 0; pi < 2; pi++) {
                uint32_t addr = smem_u32(Bb + (wn * 32 + pi * 16 + b_r) * LDA + kk + b_k);
                asm volatile("ldmatrix.sync.aligned.m8n8.x4.shared.b16 {%0,%1,%2,%3}, [%4];"
                             : "=r"(bf[pi][0]), "=r"(bf[pi][1]),
                               "=r"(bf[pi][2]), "=r"(bf[pi][3]) : "r"(addr));
            }
            #pragma unroll
            for (int mi = 0; mi < 4; mi++)
                #pragma unroll
                for (int nb = 0; nb < 4; nb++) {
                    uint32_t bb0 = bf[nb >> 1][(nb & 1) * 2];
                    uint32_t bb1 = bf[nb >> 1][(nb & 1) * 2 + 1];
                    asm volatile(
                        "mma.sync.aligned.m16n8k16.row.col.f32.f16.f16.f32 "
                        "{%0,%1,%2,%3}, {%4,%5,%6,%7}, {%8,%9}, {%0,%1,%2,%3};"
                        : "+f"(acc[mi][nb][0]), "+f"(acc[mi][nb][1]),
                          "+f"(acc[mi][nb][2]), "+f"(acc[mi][nb][3])
                        : "r"(af[mi][0]), "r"(af[mi][1]),
                          "r"(af[mi][2]), "r"(af[mi][3]),
                          "r"(bb0), "r"(bb1));
                }
        }
    };

    // full-K prefetch: all 4 stages in flight, single wait + sync
    load_stage(0, 0);
    load_stage(1, 1);
    load_stage(2, 2);
    load_stage(3, 3);

    asm volatile("cp.async.wait_group 0;\n" ::: "memory");
    __syncthreads();
    compute_stage(0);
    compute_stage(1);
    compute_stage(2);
    compute_stage(3);

    // ---- Epilogue: acc -> SMEM staging (fp16, +b1) -> coalesced stores ----
    __syncthreads();    // all reads of stage buffers complete before reuse
    __half* cst = gsm;  // [128][EPI_LD]
    const bool addb = (bn < HID);
    const int col0 = wn * 32;
    #pragma unroll
    for (int mi = 0; mi < 4; mi++) {
        #pragma unroll
        for (int nb = 0; nb < 4; nb++) {
            int r0 = wm * 64 + mi * 16 + (lane >> 2);
            int cl = col0 + nb * 8 + (lane & 3) * 2;
            float bx = addb ? __ldg(b1 + bn + cl)     : 0.0f;
            float by = addb ? __ldg(b1 + bn + cl + 1) : 0.0f;
            *(__half2*)(cst + r0 * EPI_LD + cl) =
                __floats2half2_rn(acc[mi][nb][0] + bx, acc[mi][nb][1] + by);
            *(__half2*)(cst + (r0 + 8) * EPI_LD + cl) =
                __floats2half2_rn(acc[mi][nb][2] + bx, acc[mi][nb][3] + by);
        }
    }
    __syncthreads();
    // copy-out: 128 rows x 256B, 16B per thread-chunk, fully coalesced
    #pragma unroll
    for (int i = tid; i < 128 * 16; i += 256) {
        int row = i >> 4;
        int j   = i & 15;
        if (bm + row < NNODES) {
            uint4 v = *(const uint4*)(cst + row * EPI_LD + j * 8);
            *(uint4*)(g_Ch + (size_t)(bm + row) * NCOLS + bn + j * 8) = v;
        }
    }
}

// ---------------------------------------------------------------------------
// Edge kernel (R14 config, proven): one warp per edge, 3-stage cp.async
// pipeline (HBM->SMEM, lane-private slots), W2 in registers, half2 add+relu,
// split butterfly reduction. 192-thread CTAs, 36KB smem, 6 CTAs/SM.
// ---------------------------------------------------------------------------
#define EDGE_WPB 6
#define EDGE_BLOCKS 2664     // 3 exact waves at 148 SM x 6 CTAs
#define ESTAGES 3
// per-warp stage buffer: 2KB = 128 uint4 (A half then B half)
#define EDGE_SMEM (EDGE_WPB * ESTAGES * 2048)

__global__ __launch_bounds__(EDGE_WPB * 32, 6)
void edge_kernel(const int* __restrict__ batch_r,
                 const int* __restrict__ batch_c,
                 const float* __restrict__ W2,
                 const float* __restrict__ b2,
                 float* __restrict__ out) {
    extern __shared__ uint4 dsm[];    // [EDGE_WPB warps][ESTAGES][128 uint4]

    const int tid  = threadIdx.x;
    const int warp = tid >> 5;
    const int lane = tid & 31;

    // W2 slice in registers: lane owns cols {lane*8..+7} and {(lane+32)*8..+7}
    float w0[16], w1[16];
    #pragma unroll
    for (int it = 0; it < 2; it++) {
        int cb = (lane + it * 32) * 8;
        #pragma unroll
        for (int q = 0; q < 2; q++) {
            float4 v0 = __ldg((const float4*)(W2 + cb) + q);
            float4 v1 = __ldg((const float4*)(W2 + HID + cb) + q);
            w0[it * 8 + q * 4 + 0] = v0.x; w0[it * 8 + q * 4 + 1] = v0.y;
            w0[it * 8 + q * 4 + 2] = v0.z; w0[it * 8 + q * 4 + 3] = v0.w;
            w1[it * 8 + q * 4 + 0] = v1.x; w1[it * 8 + q * 4 + 1] = v1.y;
            w1[it * 8 + q * 4 + 2] = v1.z; w1[it * 8 + q * 4 + 3] = v1.w;
        }
    }
    const float bb0 = __ldg(b2);
    const float bb1 = __ldg(b2 + 1);

    uint4* wbuf = dsm + warp * (ESTAGES * 128);
    const int gw = blockIdx.x * EDGE_WPB + warp;
    const int nw = EDGE_BLOCKS * EDGE_WPB;

    auto issue = [&](int e, int s) {
        if (e < NEDGES) {
            int r = __ldg(batch_r + e);
            int c = __ldg(batch_c + e);
            const char* pa = (const char*)(g_Ch + (size_t)r * NCOLS);
            const char* pb = (const char*)(g_Ch + (size_t)c * NCOLS + HID);
            uint32_t d = smem_u32(wbuf + s * 128) + lane * 16;
            asm volatile("cp.async.cg.shared.global [%0], [%1], 16;\n"
                         :: "r"(d), "l"(pa + lane * 16));
            asm volatile("cp.async.cg.shared.global [%0], [%1], 16;\n"
                         :: "r"(d + 512), "l"(pa + 512 + lane * 16));
            asm volatile("cp.async.cg.shared.global [%0], [%1], 16;\n"
                         :: "r"(d + 1024), "l"(pb + lane * 16));
            asm volatile("cp.async.cg.shared.global [%0], [%1], 16;\n"
                         :: "r"(d + 1536), "l"(pb + 512 + lane * 16));
        }
        asm volatile("cp.async.commit_group;\n");
    };

    issue(gw, 0);
    issue(gw + nw, 1);

    const __half2 zero2 = __float2half2_rn(0.0f);
    int s = 0;
    for (int e = gw; e < NEDGES; e += nw) {
        asm volatile("cp.async.wait_group 1;\n" ::: "memory");
        issue(e + 2 * nw, (s + 2) % ESTAGES);

        const uint4* st = wbuf + s * 128;
        uint4 a0 = st[lane];
        uint4 a1 = st[32 + lane];
        uint4 v0 = st[64 + lane];
        uint4 v1 = st[96 + lane];

        float s0 = 0.f, s1 = 0.f;
        const __half2* ha0 = (const __half2*)&a0;
        const __half2* hb0 = (const __half2*)&v0;
        const __half2* ha1 = (const __half2*)&a1;
        const __half2* hb1 = (const __half2*)&v1;
        #pragma unroll
        for (int p = 0; p < 4; p++) {
            __half2 h = __hmax2(__hadd2(ha0[p], hb0[p]), zero2);
            float2 f = __half22float2(h);
            s0 = fmaf(f.x, w0[p * 2], s0);     s1 = fmaf(f.x, w1[p * 2], s1);
            s0 = fmaf(f.y, w0[p * 2 + 1], s0); s1 = fmaf(f.y, w1[p * 2 + 1], s1);
        }
        #pragma unroll
        for (int p = 0; p < 4; p++) {
            __half2 h = __hmax2(__hadd2(ha1[p], hb1[p]), zero2);
            float2 f = __half22float2(h);
            s0 = fmaf(f.x, w0[8 + p * 2], s0);     s1 = fmaf(f.x, w1[8 + p * 2], s1);
            s0 = fmaf(f.y, w0[8 + p * 2 + 1], s0); s1 = fmaf(f.y, w1[8 + p * 2 + 1], s1);
        }

        // Split butterfly reduction: lo half folds s0, hi half folds s1.
        float o0 = __shfl_down_sync(0xffffffff, s0, 16);  // valid in lanes 0-15
        float o1 = __shfl_up_sync(0xffffffff, s1, 16);    // valid in lanes 16-31
        float v = (lane < 16) ? (s0 + o0) : (s1 + o1);
        #pragma unroll
        for (int off = 8; off > 0; off >>= 1)
            v += __shfl_xor_sync(0xffffffff, v, off);
        // lane 0 holds total s0; lane 16 holds total s1
        float vs1 = __shfl_sync(0xffffffff, v, 16);
        if (lane == 0) {
            float2 o;
            o.x = v + bb0;
            o.y = vs1 + bb1;
            *(float2*)(out + (size_t)e * OUTC) = o;
        }
        s++;
        if (s == ESTAGES) s = 0;
    }
}

// ---------------------------------------------------------------------------
// Launch
// ---------------------------------------------------------------------------
extern "C" void kernel_launch(void* const* d_in, const int* in_sizes, int n_in,
                              void* d_out, int out_size) {
    const float* z       = (const float*)d_in[0];
    const int*   batch_r = (const int*)  d_in[1];
    const int*   batch_c = (const int*)  d_in[2];
    const float* W1      = (const float*)d_in[3];
    const float* b1      = (const float*)d_in[4];
    const float* W2      = (const float*)d_in[5];
    const float* b2      = (const float*)d_in[6];
    float* out = (float*)d_out;

    // Idempotent, capture-safe host-side attributes.
    cudaFuncSetAttribute(gemm_hmma_kernel,
                         cudaFuncAttributeMaxDynamicSharedMemorySize, GEMM_SMEM);
    cudaFuncSetAttribute(edge_kernel,
                         cudaFuncAttributeMaxDynamicSharedMemorySize, EDGE_SMEM);

    // 1) fp16 operand prep (merged A+B, MLP=4)
    prep_kernel<<<(PREP_TOTAL + 1023) / 1024, 256>>>(z, W1);

    // 2) C = A @ B^T (+b1), fp16 out
    dim3 ggrid(NCOLS / BN, (NNODES + BM - 1) / BM);
    gemm_hmma_kernel<<<ggrid, 256, GEMM_SMEM>>>(b1);

    // 3) Fused edge decode (pipelined gather)
    edge_kernel<<<EDGE_BLOCKS, EDGE_WPB * 32, EDGE_SMEM>>>(batch_r, batch_c, W2, b2, out);
}

// round 16
// speedup vs baseline: 1.0352x; 1.0352x over previous
#include <cuda_runtime.h>
#include <cuda_fp16.h>
#include <cstdint>

// Problem constants
#define NNODES 100000
#define NEDGES 500000
#define DZ     128
#define HID    512
#define NCOLS  1024     // [A | B] per node
#define OUTC   2
#define KTOT   128      // plain fp16 K

// Scratch (static device arrays: allocation-free per harness rules)
__device__ __half g_Ch[(size_t)NNODES * NCOLS];   // C = [A|B] in fp16 (205 MB)
__device__ __half g_A[(size_t)NNODES * KTOT];     // z in fp16 (25.6 MB)
__device__ __half g_B[(size_t)NCOLS  * KTOT];     // W1 reshaped, fp16 (256 KB)

__device__ __forceinline__ uint32_t smem_u32(const void* p) {
    uint32_t a;
    asm("{ .reg .u64 t; cvta.to.shared.u64 t, %1; cvt.u32.u64 %0, t; }"
        : "=r"(a) : "l"(p));
    return a;
}

__device__ __forceinline__ uint2 cvt4_fp16(float4 v) {
    uint16_t h[4];
    h[0] = __half_as_ushort(__float2half_rn(v.x));
    h[1] = __half_as_ushort(__float2half_rn(v.y));
    h[2] = __half_as_ushort(__float2half_rn(v.z));
    h[3] = __half_as_ushort(__float2half_rn(v.w));
    uint2 p;
    p.x = (uint32_t)h[0] | ((uint32_t)h[1] << 16);
    p.y = (uint32_t)h[2] | ((uint32_t)h[3] << 16);
    return p;
}

// ---------------------------------------------------------------------------
// Prep (merged, R14 form): A-part converts z -> fp16 [NNODES,128];
// B-part reshapes W1 rows -> fp16 [NCOLS,128].
// ---------------------------------------------------------------------------
#define PREP_A_WORK (NNODES * 32)
#define PREP_B_WORK (NCOLS * 32)

__global__ __launch_bounds__(256)
void prep_kernel(const float* __restrict__ z, const float* __restrict__ W1) {
    int idx = blockIdx.x * blockDim.x + threadIdx.x;
    if (idx < PREP_A_WORK) {
        float4 v = __ldg(((const float4*)z) + idx);
        *(uint2*)(g_A + (size_t)idx * 4) = cvt4_fp16(v);
    } else if (idx < PREP_A_WORK + PREP_B_WORK) {
        int i2 = idx - PREP_A_WORK;
        int n = i2 >> 5;
        int c4 = i2 & 31;
        const float4* src = (n < HID)
            ? ((const float4*)W1 + n * 64 + c4)
            : ((const float4*)W1 + (n - HID) * 64 + 32 + c4);
        float4 v = __ldg(src);
        *(uint2*)(g_B + (size_t)n * KTOT + c4 * 4) = cvt4_fp16(v);
    }
}

// ---------------------------------------------------------------------------
// HMMA GEMM (R14 schedule): C[M,1024] = A[M,128] @ B[1024,128]^T (+ b1 on
// cols < 512), stored fp16. Tile 128x128x32, 256 threads (8 warps, 64x32),
// mma.m16n8k16 fp16 (fp32 acc), 4-stage full-K cp.async prefetch with
// staggered waits (2/2/1/0), SMEM-staged coalesced epilogue.
// ---------------------------------------------------------------------------
#define BM 128
#define BN 128
#define BK 32
#define LDA 40            // smem row stride in halfs (conflict-free ldmatrix)
#define GSTAGE (BM * LDA) // halfs per operand stage = 5120
#define GEMM_SMEM (8 * GSTAGE * 2)   // 4 A-stages + 4 B-stages = 81920 B
#define EPI_LD 136        // epilogue staging row stride (halfs), conflict-free

__global__ __launch_bounds__(256, 2)
void gemm_hmma_kernel(const float* __restrict__ b1) {
    extern __shared__ __half gsm[];
    __half* As = gsm;                 // [4][GSTAGE]
    __half* Bs = gsm + 4 * GSTAGE;    // [4][GSTAGE]

    const int tid  = threadIdx.x;
    const int lane = tid & 31;
    const int wid  = tid >> 5;
    const int wm   = wid >> 2;       // 0..1 -> m offset wm*64
    const int wn   = wid & 3;        // 0..3 -> n offset wn*32
    const int bn   = blockIdx.x * BN;   // x = n-tile so concurrent CTAs share A
    const int bm   = blockIdx.y * BM;

    float acc[4][4][4];
    #pragma unroll
    for (int i = 0; i < 4; i++)
        #pragma unroll
        for (int j = 0; j < 4; j++)
            #pragma unroll
            for (int k = 0; k < 4; k++) acc[i][j][k] = 0.0f;

    const int a_r = lane & 15;
    const int a_k = (lane >> 4) * 8;
    const int b_r = (lane & 7) + (lane >> 4) * 8;
    const int b_k = ((lane >> 3) & 1) * 8;

    auto load_stage = [&](int it, int buf) {
        const int k0 = it * BK;
        #pragma unroll
        for (int j = 0; j < 2; j++) {
            int li  = tid + j * 256;      // 0..511 over 128 rows x 4 chunks
            int row = li >> 2;
            int ch  = (li & 3) * 8;
            uint32_t da = smem_u32(As + buf * GSTAGE + row * LDA + ch);
            const __half* sa = g_A + (size_t)(bm + row) * KTOT + k0 + ch;
            int sz = (bm + row < NNODES) ? 16 : 0;
            asm volatile("cp.async.cg.shared.global [%0], [%1], 16, %2;\n"
                         :: "r"(da), "l"(sa), "r"(sz));
            uint32_t db = smem_u32(Bs + buf * GSTAGE + row * LDA + ch);
            const __half* sb = g_B + (size_t)(bn + row) * KTOT + k0 + ch;
            asm volatile("cp.async.cg.shared.global [%0], [%1], 16;\n"
                         :: "r"(db), "l"(sb));
        }
        asm volatile("cp.async.commit_group;\n");
    };

    auto compute_stage = [&](int buf) {
        const __half* Ab = As + buf * GSTAGE;
        const __half* Bb = Bs + buf * GSTAGE;
        #pragma unroll
        for (int kk = 0; kk < BK; kk += 16) {
            uint32_t af[4][4], bf[2][4];
            #pragma unroll
            for (int mi = 0; mi < 4; mi++) {
                uint32_t addr = smem_u32(Ab + (wm * 64 + mi * 16 + a_r) * LDA + kk + a_k);
                asm volatile("ldmatrix.sync.aligned.m8n8.x4.shared.b16 {%0,%1,%2,%3}, [%4];"
                             : "=r"(af[mi][0]), "=r"(af[mi][1]),
                               "=r"(af[mi][2]), "=r"(af[mi][3]) : "r"(addr));
            }
            #pragma unroll
            for (int pi = 0; pi < 2; pi++) {
                uint32_t addr = smem_u32(Bb + (wn * 32 + pi * 16 + b_r) * LDA + kk + b_k);
                asm volatile("ldmatrix.sync.aligned.m8n8.x4.shared.b16 {%0,%1,%2,%3}, [%4];"
                             : "=r"(bf[pi][0]), "=r"(bf[pi][1]),
                               "=r"(bf[pi][2]), "=r"(bf[pi][3]) : "r"(addr));
            }
            #pragma unroll
            for (int mi = 0; mi < 4; mi++)
                #pragma unroll
                for (int nb = 0; nb < 4; nb++) {
                    uint32_t bb0 = bf[nb >> 1][(nb & 1) * 2];
                    uint32_t bb1 = bf[nb >> 1][(nb & 1) * 2 + 1];
                    asm volatile(
                        "mma.sync.aligned.m16n8k16.row.col.f32.f16.f16.f32 "
                        "{%0,%1,%2,%3}, {%4,%5,%6,%7}, {%8,%9}, {%0,%1,%2,%3};"
                        : "+f"(acc[mi][nb][0]), "+f"(acc[mi][nb][1]),
                          "+f"(acc[mi][nb][2]), "+f"(acc[mi][nb][3])
                        : "r"(af[mi][0]), "r"(af[mi][1]),
                          "r"(af[mi][2]), "r"(af[mi][3]),
                          "r"(bb0), "r"(bb1));
                }
        }
    };

    // full-K prefetch: issue 3 stages up front, staggered waits (R14 proven)
    load_stage(0, 0);
    load_stage(1, 1);
    load_stage(2, 2);

    asm volatile("cp.async.wait_group 2;\n" ::: "memory");
    __syncthreads();
    load_stage(3, 3);
    compute_stage(0);

    asm volatile("cp.async.wait_group 2;\n" ::: "memory");
    __syncthreads();
    compute_stage(1);

    asm volatile("cp.async.wait_group 1;\n" ::: "memory");
    __syncthreads();
    compute_stage(2);

    asm volatile("cp.async.wait_group 0;\n" ::: "memory");
    __syncthreads();
    compute_stage(3);

    // ---- Epilogue: acc -> SMEM staging (fp16, +b1) -> coalesced stores ----
    __syncthreads();    // all reads of stage buffers complete before reuse
    __half* cst = gsm;  // [128][EPI_LD]
    const bool addb = (bn < HID);
    const int col0 = wn * 32;
    #pragma unroll
    for (int mi = 0; mi < 4; mi++) {
        #pragma unroll
        for (int nb = 0; nb < 4; nb++) {
            int r0 = wm * 64 + mi * 16 + (lane >> 2);
            int cl = col0 + nb * 8 + (lane & 3) * 2;
            float bx = addb ? __ldg(b1 + bn + cl)     : 0.0f;
            float by = addb ? __ldg(b1 + bn + cl + 1) : 0.0f;
            *(__half2*)(cst + r0 * EPI_LD + cl) =
                __floats2half2_rn(acc[mi][nb][0] + bx, acc[mi][nb][1] + by);
            *(__half2*)(cst + (r0 + 8) * EPI_LD + cl) =
                __floats2half2_rn(acc[mi][nb][2] + bx, acc[mi][nb][3] + by);
        }
    }
    __syncthreads();
    // copy-out: 128 rows x 256B, 16B per thread-chunk, fully coalesced
    #pragma unroll
    for (int i = tid; i < 128 * 16; i += 256) {
        int row = i >> 4;
        int j   = i & 15;
        if (bm + row < NNODES) {
            uint4 v = *(const uint4*)(cst + row * EPI_LD + j * 8);
            *(uint4*)(g_Ch + (size_t)(bm + row) * NCOLS + bn + j * 8) = v;
        }
    }
}

// ---------------------------------------------------------------------------
// Edge kernel (R14 config + index prefetch): one warp per edge, 3-stage
// cp.async pipeline (HBM->SMEM, lane-private slots), W2 in registers,
// half2 add+relu, split butterfly reduction. The (r,c) indices for the NEXT
// issue are prefetched one iteration ahead so their LDG latency overlaps
// compute instead of stalling the issue path.
// ---------------------------------------------------------------------------
#define EDGE_WPB 6
#define EDGE_BLOCKS 2664     // 3 exact waves at 148 SM x 6 CTAs
#define ESTAGES 3
// per-warp stage buffer: 2KB = 128 uint4 (A half then B half)
#define EDGE_SMEM (EDGE_WPB * ESTAGES * 2048)

__global__ __launch_bounds__(EDGE_WPB * 32, 6)
void edge_kernel(const int* __restrict__ batch_r,
                 const int* __restrict__ batch_c,
                 const float* __restrict__ W2,
                 const float* __restrict__ b2,
                 float* __restrict__ out) {
    extern __shared__ uint4 dsm[];    // [EDGE_WPB warps][ESTAGES][128 uint4]

    const int tid  = threadIdx.x;
    const int warp = tid >> 5;
    const int lane = tid & 31;

    // W2 slice in registers: lane owns cols {lane*8..+7} and {(lane+32)*8..+7}
    float w0[16], w1[16];
    #pragma unroll
    for (int it = 0; it < 2; it++) {
        int cb = (lane + it * 32) * 8;
        #pragma unroll
        for (int q = 0; q < 2; q++) {
            float4 v0 = __ldg((const float4*)(W2 + cb) + q);
            float4 v1 = __ldg((const float4*)(W2 + HID + cb) + q);
            w0[it * 8 + q * 4 + 0] = v0.x; w0[it * 8 + q * 4 + 1] = v0.y;
            w0[it * 8 + q * 4 + 2] = v0.z; w0[it * 8 + q * 4 + 3] = v0.w;
            w1[it * 8 + q * 4 + 0] = v1.x; w1[it * 8 + q * 4 + 1] = v1.y;
            w1[it * 8 + q * 4 + 2] = v1.z; w1[it * 8 + q * 4 + 3] = v1.w;
        }
    }
    const float bb0 = __ldg(b2);
    const float bb1 = __ldg(b2 + 1);

    uint4* wbuf = dsm + warp * (ESTAGES * 128);
    const int gw = blockIdx.x * EDGE_WPB + warp;
    const int nw = EDGE_BLOCKS * EDGE_WPB;

    // prefetch edge indices (safe index 0 for OOB; result unused then)
    auto pref = [&](int e, int& r, int& c) {
        int idx = (e < NEDGES) ? e : 0;
        r = __ldg(batch_r + idx);
        c = __ldg(batch_c + idx);
    };

    // issue with pre-loaded indices
    auto issue = [&](int e, int s, int r, int c) {
        if (e < NEDGES) {
            const char* pa = (const char*)(g_Ch + (size_t)r * NCOLS);
            const char* pb = (const char*)(g_Ch + (size_t)c * NCOLS + HID);
            uint32_t d = smem_u32(wbuf + s * 128) + lane * 16;
            asm volatile("cp.async.cg.shared.global [%0], [%1], 16;\n"
                         :: "r"(d), "l"(pa + lane * 16));
            asm volatile("cp.async.cg.shared.global [%0], [%1], 16;\n"
                         :: "r"(d + 512), "l"(pa + 512 + lane * 16));
            asm volatile("cp.async.cg.shared.global [%0], [%1], 16;\n"
                         :: "r"(d + 1024), "l"(pb + lane * 16));
            asm volatile("cp.async.cg.shared.global [%0], [%1], 16;\n"
                         :: "r"(d + 1536), "l"(pb + 512 + lane * 16));
        }
        asm volatile("cp.async.commit_group;\n");
    };

    {
        int r, c;
        pref(gw, r, c);
        issue(gw, 0, r, c);
        pref(gw + nw, r, c);
        issue(gw + nw, 1, r, c);
    }
    int nr, nc;
    pref(gw + 2 * nw, nr, nc);

    const __half2 zero2 = __float2half2_rn(0.0f);
    int s = 0;
    for (int e = gw; e < NEDGES; e += nw) {
        asm volatile("cp.async.wait_group 1;\n" ::: "memory");
        issue(e + 2 * nw, (s + 2) % ESTAGES, nr, nc);
        pref(e + 3 * nw, nr, nc);   // LDG latency overlaps compute below

        const uint4* st = wbuf + s * 128;
        uint4 a0 = st[lane];
        uint4 a1 = st[32 + lane];
        uint4 v0 = st[64 + lane];
        uint4 v1 = st[96 + lane];

        float s0 = 0.f, s1 = 0.f;
        const __half2* ha0 = (const __half2*)&a0;
        const __half2* hb0 = (const __half2*)&v0;
        const __half2* ha1 = (const __half2*)&a1;
        const __half2* hb1 = (const __half2*)&v1;
        #pragma unroll
        for (int p = 0; p < 4; p++) {
            __half2 h = __hmax2(__hadd2(ha0[p], hb0[p]), zero2);
            float2 f = __half22float2(h);
            s0 = fmaf(f.x, w0[p * 2], s0);     s1 = fmaf(f.x, w1[p * 2], s1);
            s0 = fmaf(f.y, w0[p * 2 + 1], s0); s1 = fmaf(f.y, w1[p * 2 + 1], s1);
        }
        #pragma unroll
        for (int p = 0; p < 4; p++) {
            __half2 h = __hmax2(__hadd2(ha1[p], hb1[p]), zero2);
            float2 f = __half22float2(h);
            s0 = fmaf(f.x, w0[8 + p * 2], s0);     s1 = fmaf(f.x, w1[8 + p * 2], s1);
            s0 = fmaf(f.y, w0[8 + p * 2 + 1], s0); s1 = fmaf(f.y, w1[8 + p * 2 + 1], s1);
        }

        // Split butterfly reduction: lo half folds s0, hi half folds s1.
        float o0 = __shfl_down_sync(0xffffffff, s0, 16);  // valid in lanes 0-15
        float o1 = __shfl_up_sync(0xffffffff, s1, 16);    // valid in lanes 16-31
        float v = (lane < 16) ? (s0 + o0) : (s1 + o1);
        #pragma unroll
        for (int off = 8; off > 0; off >>= 1)
            v += __shfl_xor_sync(0xffffffff, v, off);
        // lane 0 holds total s0; lane 16 holds total s1
        float vs1 = __shfl_sync(0xffffffff, v, 16);
        if (lane == 0) {
            float2 o;
            o.x = v + bb0;
            o.y = vs1 + bb1;
            *(float2*)(out + (size_t)e * OUTC) = o;
        }
        s++;
        if (s == ESTAGES) s = 0;
    }
}

// ---------------------------------------------------------------------------
// Launch
// ---------------------------------------------------------------------------
extern "C" void kernel_launch(void* const* d_in, const int* in_sizes, int n_in,
                              void* d_out, int out_size) {
    const float* z       = (const float*)d_in[0];
    const int*   batch_r = (const int*)  d_in[1];
    const int*   batch_c = (const int*)  d_in[2];
    const float* W1      = (const float*)d_in[3];
    const float* b1      = (const float*)d_in[4];
    const float* W2      = (const float*)d_in[5];
    const float* b2      = (const float*)d_in[6];
    float* out = (float*)d_out;

    // Idempotent, capture-safe host-side attributes.
    cudaFuncSetAttribute(gemm_hmma_kernel,
                         cudaFuncAttributeMaxDynamicSharedMemorySize, GEMM_SMEM);
    cudaFuncSetAttribute(edge_kernel,
                         cudaFuncAttributeMaxDynamicSharedMemorySize, EDGE_SMEM);

    // 1) fp16 operand prep (merged A+B)
    prep_kernel<<<(PREP_A_WORK + PREP_B_WORK + 255) / 256, 256>>>(z, W1);

    // 2) C = A @ B^T (+b1), fp16 out
    dim3 ggrid(NCOLS / BN, (NNODES + BM - 1) / BM);
    gemm_hmma_kernel<<<ggrid, 256, GEMM_SMEM>>>(b1);

    // 3) Fused edge decode (pipelined gather, index-prefetched)
    edge_kernel<<<EDGE_BLOCKS, EDGE_WPB * 32, EDGE_SMEM>>>(batch_r, batch_c, W2, b2, out);
}